// round 13
// baseline (speedup 1.0000x reference)
#include <cuda_runtime.h>
#include <cuda_bf16.h>
#include <math_constants.h>
#include <cstdint>

// Problem constants (fixed by the dataset)
#define NN      50000
#define NE      1600000
#define NETOT   (NE + NN)      // edges + self loops
#define NGRAPHS 64

#define SCHUNK  512
#define SBLOCKS ((NN + SCHUNK - 1) / SCHUNK)   // 98

// ---------------- scratch (static device globals; no allocs allowed) --------
__device__ float g_xl[NN * 64];
__device__ float g_xr[NN * 64];
__device__ float g_h1[NN * 64];
__device__ float g_h2[NN * 64];
__device__ float g_h3[NN * 10];
__device__ int   g_counts[NN];
__device__ int   g_offsets[NN + 1];
__device__ int   g_cursor[NN];
__device__ int   g_csr_src[NETOT + 64];   // +pad: allows unconditional prefetch
__device__ volatile int g_blk_inc[SBLOCKS];   // chained-scan inclusive prefixes
__device__ volatile int g_blk_flag[SBLOCKS];  // chained-scan ready flags
__device__ int   g_is64;   // 1 if index inputs are stored as int64 words

// Device-side scratch selector: ids 0=xl 1=xr 2=h1 3=h2 4=h3
__device__ __forceinline__ float* scratch(int id) {
    switch (id) {
        case 0: return g_xl;
        case 1: return g_xr;
        case 2: return g_h1;
        case 3: return g_h2;
        default: return g_h3;
    }
}

// ---------------- tf32 helpers ----------------------------------------------
__device__ __forceinline__ float tf32r(float x) {
    unsigned int u;
    asm("cvt.rna.tf32.f32 %0, %1;" : "=r"(u) : "f"(x));
    return __uint_as_float(u);
}

__device__ __forceinline__ void mma_tf32(float* c, const unsigned int* a,
                                         unsigned int b0, unsigned int b1) {
    asm volatile(
        "mma.sync.aligned.m16n8k8.row.col.f32.tf32.tf32.f32 "
        "{%0,%1,%2,%3}, {%4,%5,%6,%7}, {%8,%9}, {%0,%1,%2,%3};"
        : "+f"(c[0]), "+f"(c[1]), "+f"(c[2]), "+f"(c[3])
        : "r"(a[0]), "r"(a[1]), "r"(a[2]), "r"(a[3]), "r"(b0), "r"(b1));
}

__device__ __forceinline__ float lrelu02(float t) {
    return fmaxf(t, 0.f) + 0.2f * fminf(t, 0.f);
}

// ---------------- init: counts, pad, scan flags, dtype sniff ----------------
__global__ void init_kernel(const int* __restrict__ w, int n) {
    int i = blockIdx.x * blockDim.x + threadIdx.x;
    if (i < n) g_counts[i] = 1;            // self loop pre-counted
    if (i < 64) g_csr_src[NETOT + i] = 0;  // safe pad for prefetch
    if (i < SBLOCKS) { g_blk_flag[i] = 0; g_blk_inc[i] = 0; }
    if (i == 0) {
        int acc = 0;
#pragma unroll
        for (int k = 1; k < 128; k += 2) acc |= w[k];
        g_is64 = (acc == 0) ? 1 : 0;
    }
}

// ---------------- hist: 2 edges per thread ----------------------------------
__global__ void hist_kernel(const int* __restrict__ ei) {
    int t = blockIdx.x * blockDim.x + threadIdx.x;
    if (t < NE / 2) {
        int d0, d1;
        if (g_is64) {
            int4 v = ((const int4*)ei)[(NE / 2) + t];  // dst words of edges 2t,2t+1
            d0 = v.x; d1 = v.z;
        } else {
            int2 v = ((const int2*)ei)[(NE / 2) + t];
            d0 = v.x; d1 = v.y;
        }
        if ((unsigned)d0 < (unsigned)NN) atomicAdd(&g_counts[d0], 1);
        if ((unsigned)d1 < (unsigned)NN) atomicAdd(&g_counts[d1], 1);
    }
}

// ---- single-pass chained scan: offsets, cursor, self-loop placement --------
// All SBLOCKS=98 blocks are co-resident (<=148 SMs) -> chained spin is safe.
__global__ __launch_bounds__(SCHUNK)
void scan_single_kernel(int n) {
    __shared__ int sh[SCHUNK];
    __shared__ int s_prev;
    int b = blockIdx.x, tid = threadIdx.x;
    int i = b * SCHUNK + tid;
    int v = (i < n) ? g_counts[i] : 0;
    sh[tid] = v;
    __syncthreads();
#pragma unroll
    for (int o = 1; o < SCHUNK; o <<= 1) {
        int t = (tid >= o) ? sh[tid - o] : 0;
        __syncthreads();
        sh[tid] += t;
        __syncthreads();
    }
    // block total = sh[SCHUNK-1]; chain through predecessor
    if (tid == 0) {
        int prev = 0;
        if (b > 0) {
            while (g_blk_flag[b - 1] == 0) { }   // all blocks resident: no deadlock
            prev = g_blk_inc[b - 1];
        }
        s_prev = prev;
        g_blk_inc[b] = prev + sh[SCHUNK - 1];
        __threadfence();
        g_blk_flag[b] = 1;
        if (b == SBLOCKS - 1) g_offsets[NN] = prev + sh[SCHUNK - 1];
    }
    __syncthreads();
    int prev = s_prev;
    if (i < n) {
        int excl = prev + sh[tid] - v;
        g_offsets[i] = excl;
        g_csr_src[excl] = i;        // self loop at segment head
        g_cursor[i]  = excl + 1;
    }
}

// ---------------- scatter: 2 edges per thread --------------------------------
__global__ void scatter_kernel(const int* __restrict__ ei) {
    int t = blockIdx.x * blockDim.x + threadIdx.x;
    if (t < NE / 2) {
        int s0, s1, d0, d1;
        if (g_is64) {
            int4 sv = ((const int4*)ei)[t];             // src words of edges 2t,2t+1
            int4 dv = ((const int4*)ei)[(NE / 2) + t];  // dst words
            s0 = sv.x; s1 = sv.z;
            d0 = dv.x; d1 = dv.z;
        } else {
            int2 sv = ((const int2*)ei)[t];
            int2 dv = ((const int2*)ei)[(NE / 2) + t];
            s0 = sv.x; s1 = sv.y;
            d0 = dv.x; d1 = dv.y;
        }
        if ((unsigned)d0 < (unsigned)NN && (unsigned)s0 < (unsigned)NN) {
            int pos = atomicAdd(&g_cursor[d0], 1);
            g_csr_src[pos] = s0;
        }
        if ((unsigned)d1 < (unsigned)NN && (unsigned)s1 < (unsigned)NN) {
            int pos = atomicAdd(&g_cursor[d1], 1);
            g_csr_src[pos] = s1;
        }
    }
}

// ---------------- dual GEMM via tf32 tensor cores ---------------------------
// Yl = X@Wl+Bl, Yr = X@Wr+Br (OC=64 each). Output treated as concat 128 cols.
// CTA: 256 thr = 8 warps; warp w -> rows (w&3)*32..+31, cols (w>>2)*64..+63.
template<int K>
__global__ __launch_bounds__(256)
void gemm_dual_tf32_kernel(const float* __restrict__ Xext, int xid,
                           const float* __restrict__ Wl, const float* __restrict__ Bl,
                           const float* __restrict__ Wr, const float* __restrict__ Br,
                           int n)
{
    const float* __restrict__ X = Xext ? Xext : scratch(xid);

    __shared__ float sX[16][136];   // [k][row], stride 136 -> conflict-free frags
    __shared__ float sW[16][136];   // [k][col] concat (0..63 Wl, 64..127 Wr)

    int tid  = threadIdx.x;
    int lane = tid & 31;
    int w    = tid >> 5;
    int gid  = lane >> 2;     // 0..7
    int tig  = lane & 3;      // 0..3
    int rbase = (w & 3) * 32;
    int cbase = (w >> 2) * 64;
    int row0  = blockIdx.x * 128;

    float c[2][8][4];
#pragma unroll
    for (int t = 0; t < 2; ++t)
#pragma unroll
        for (int nt = 0; nt < 8; ++nt)
#pragma unroll
            for (int q = 0; q < 4; ++q) c[t][nt][q] = 0.f;

    int srow = tid & 127;            // staging row 0..127
    int ksub = (tid >> 7) * 8;       // 0 or 8

    for (int kc = 0; kc < K; kc += 16) {
        // ---- global loads (no smem touched yet) ----
        float4 v0 = make_float4(0.f, 0.f, 0.f, 0.f);
        float4 v1 = make_float4(0.f, 0.f, 0.f, 0.f);
        int grow = row0 + srow;
        if (grow < n) {
            v0 = *(const float4*)(X + (size_t)grow * K + kc + ksub);
            v1 = *(const float4*)(X + (size_t)grow * K + kc + ksub + 4);
        }
        float4 wv[2]; int wk[2], wc4[2];
#pragma unroll
        for (int t = 0; t < 2; ++t) {
            int i = tid + t * 256;
            wk[t]  = i >> 5;
            wc4[t] = (i & 31) << 2;
            wv[t] = (wc4[t] < 64)
                  ? *(const float4*)(Wl + (size_t)(kc + wk[t]) * 64 + wc4[t])
                  : *(const float4*)(Wr + (size_t)(kc + wk[t]) * 64 + (wc4[t] - 64));
        }
        __syncthreads();   // prior compute done before overwriting smem
        // ---- stage with tf32 rounding ----
        sX[ksub + 0][srow] = tf32r(v0.x);
        sX[ksub + 1][srow] = tf32r(v0.y);
        sX[ksub + 2][srow] = tf32r(v0.z);
        sX[ksub + 3][srow] = tf32r(v0.w);
        sX[ksub + 4][srow] = tf32r(v1.x);
        sX[ksub + 5][srow] = tf32r(v1.y);
        sX[ksub + 6][srow] = tf32r(v1.z);
        sX[ksub + 7][srow] = tf32r(v1.w);
#pragma unroll
        for (int t = 0; t < 2; ++t) {
            sW[wk[t]][wc4[t] + 0] = tf32r(wv[t].x);
            sW[wk[t]][wc4[t] + 1] = tf32r(wv[t].y);
            sW[wk[t]][wc4[t] + 2] = tf32r(wv[t].z);
            sW[wk[t]][wc4[t] + 3] = tf32r(wv[t].w);
        }
        __syncthreads();
        // ---- compute 2 k8 sub-blocks ----
#pragma unroll
        for (int k8 = 0; k8 < 16; k8 += 8) {
            unsigned int a[2][4];
#pragma unroll
            for (int t = 0; t < 2; ++t) {
                int r = rbase + t * 16;
                a[t][0] = __float_as_uint(sX[k8 + tig][r + gid]);
                a[t][1] = __float_as_uint(sX[k8 + tig][r + gid + 8]);
                a[t][2] = __float_as_uint(sX[k8 + tig + 4][r + gid]);
                a[t][3] = __float_as_uint(sX[k8 + tig + 4][r + gid + 8]);
            }
#pragma unroll
            for (int nt = 0; nt < 8; ++nt) {
                unsigned int b0 = __float_as_uint(sW[k8 + tig][cbase + nt * 8 + gid]);
                unsigned int b1 = __float_as_uint(sW[k8 + tig + 4][cbase + nt * 8 + gid]);
                mma_tf32(c[0][nt], a[0], b0, b1);
                mma_tf32(c[1][nt], a[1], b0, b1);
            }
        }
    }

    // ---- epilogue: bias + split into Yl/Yr ----
#pragma unroll
    for (int nt = 0; nt < 8; ++nt) {
        int col = cbase + nt * 8 + tig * 2;
        bool isR = col >= 64;
        int lc = isR ? (col - 64) : col;
        float* __restrict__ Y = isR ? g_xr : g_xl;
        const float* __restrict__ Bb = isR ? Br : Bl;
        float bx = __ldg(Bb + lc);
        float by = __ldg(Bb + lc + 1);
#pragma unroll
        for (int t = 0; t < 2; ++t) {
            int r0 = row0 + rbase + t * 16 + gid;
            if (r0 < n) {
                *(float2*)(Y + (size_t)r0 * 64 + lc) =
                    make_float2(c[t][nt][0] + bx, c[t][nt][1] + by);
            }
            int r1 = r0 + 8;
            if (r1 < n) {
                *(float2*)(Y + (size_t)r1 * 64 + lc) =
                    make_float2(c[t][nt][2] + bx, c[t][nt][3] + by);
            }
        }
    }
}

// dual small GEMM: Yl = X@Wl+Bl, Yr = X@Wr+Br, OC=10, K=64. X = g_h2.
__global__ __launch_bounds__(128)
void gemm_small10_dual_kernel(const float* __restrict__ Wl, const float* __restrict__ Bl,
                              const float* __restrict__ Wr, const float* __restrict__ Br,
                              int n)
{
    const float* __restrict__ X = g_h2;
    float* __restrict__ Yl = g_xl;
    float* __restrict__ Yr = g_xr;

    __shared__ float sWl[64][10];
    __shared__ float sWr[64][10];
    __shared__ float sX[128][65];
    int tid = threadIdx.x;
    for (int i = tid; i < 640; i += 128) {
        sWl[i / 10][i % 10] = Wl[i];
        sWr[i / 10][i % 10] = Wr[i];
    }
    int row0 = blockIdx.x * 128;
    for (int i = tid; i < 2048; i += 128) {
        int r = i >> 4, c4 = (i & 15) << 2;
        int gr = row0 + r;
        float4 v = make_float4(0.f, 0.f, 0.f, 0.f);
        if (gr < n) v = *(const float4*)(X + (size_t)gr * 64 + c4);
        sX[r][c4 + 0] = v.x; sX[r][c4 + 1] = v.y;
        sX[r][c4 + 2] = v.z; sX[r][c4 + 3] = v.w;
    }
    __syncthreads();
    int row = row0 + tid;
    float accl[10], accr[10];
#pragma unroll
    for (int c = 0; c < 10; ++c) { accl[c] = 0.f; accr[c] = 0.f; }
#pragma unroll 4
    for (int k = 0; k < 64; ++k) {
        float a = sX[tid][k];
#pragma unroll
        for (int c = 0; c < 10; ++c) {
            accl[c] = fmaf(a, sWl[k][c], accl[c]);
            accr[c] = fmaf(a, sWr[k][c], accr[c]);
        }
    }
    if (row < n) {
#pragma unroll
        for (int c = 0; c < 10; ++c) {
            Yl[(size_t)row * 10 + c] = accl[c] + Bl[c];
            Yr[(size_t)row * 10 + c] = accr[c] + Br[c];
        }
    }
}

// ---------------- GATv2 edge kernel v3, H=2, C=32 ---------------------------
// Warp per node, 4 edges per iteration: slot = lane>>3 (edge), c = lane&7
// (feature chunk: floats [8c, 8c+8) = two float4s). Head 0 = lanes c 0..3,
// head 1 = lanes c 4..7 -> logit reduction is xor 2, xor 1 ONLY (per-head).
// Branchless online softmax per (slot, head); slots merged via xor 8, xor 16
// (flips slot bits only, so merges stay head-consistent).
__global__ __launch_bounds__(256)
void gat_h2c32_kernel(int oid, const float* __restrict__ att,
                      const float* __restrict__ bias, int n)
{
    const float4* __restrict__ xl4 = (const float4*)g_xl;
    float* __restrict__ out = scratch(oid);

    int node = (blockIdx.x * blockDim.x + threadIdx.x) >> 5;
    if (node >= n) return;
    int lane = threadIdx.x & 31;
    int c    = lane & 7;      // chunk pair id (0..7); head = c>>2
    int slot = lane >> 3;     // 0..3

    const float4* xr4 = (const float4*)(g_xr + (size_t)node * 64);
    float4 xrv0 = xr4[2 * c], xrv1 = xr4[2 * c + 1];
    float4 av0 = ((const float4*)att)[2 * c];
    float4 av1 = ((const float4*)att)[2 * c + 1];

    int j  = g_offsets[node];
    const int j1 = g_offsets[node + 1];

    float m = -1e30f, s = 0.f;
    float4 acc0 = make_float4(0.f, 0.f, 0.f, 0.f);
    float4 acc1 = make_float4(0.f, 0.f, 0.f, 0.f);

    int src = g_csr_src[j + slot];
    float4 cur0 = xl4[(size_t)src * 16 + 2 * c];
    float4 cur1 = xl4[(size_t)src * 16 + 2 * c + 1];

    while (j < j1) {
        int jn = j + 4;
        int nsrc = g_csr_src[jn + slot];                   // padded: always safe
        float4 ncur0 = xl4[(size_t)nsrc * 16 + 2 * c];     // prefetch next gather
        float4 ncur1 = xl4[(size_t)nsrc * 16 + 2 * c + 1];

        float v;
        {
            float t;
            t = cur0.x + xrv0.x; v  = lrelu02(t) * av0.x;
            t = cur0.y + xrv0.y; v  = fmaf(lrelu02(t), av0.y, v);
            t = cur0.z + xrv0.z; v  = fmaf(lrelu02(t), av0.z, v);
            t = cur0.w + xrv0.w; v  = fmaf(lrelu02(t), av0.w, v);
            t = cur1.x + xrv1.x; v  = fmaf(lrelu02(t), av1.x, v);
            t = cur1.y + xrv1.y; v  = fmaf(lrelu02(t), av1.y, v);
            t = cur1.z + xrv1.z; v  = fmaf(lrelu02(t), av1.z, v);
            t = cur1.w + xrv1.w; v  = fmaf(lrelu02(t), av1.w, v);
        }
        // per-head reduction: heads occupy 4-lane groups -> xor 2, xor 1 only
        v += __shfl_xor_sync(0xffffffffu, v, 2);
        v += __shfl_xor_sync(0xffffffffu, v, 1);
        if (j + slot >= j1) v = -2e30f;    // ragged-tail sentinel: zero contribution

        float d  = v - m;
        float e  = __expf(-fabsf(d));
        float cf = (d > 0.f) ? e : 1.f;
        float p  = (d > 0.f) ? 1.f : e;
        m = fmaxf(m, v);
        s = fmaf(s, cf, p);
        acc0.x = fmaf(acc0.x, cf, p * cur0.x);
        acc0.y = fmaf(acc0.y, cf, p * cur0.y);
        acc0.z = fmaf(acc0.z, cf, p * cur0.z);
        acc0.w = fmaf(acc0.w, cf, p * cur0.w);
        acc1.x = fmaf(acc1.x, cf, p * cur1.x);
        acc1.y = fmaf(acc1.y, cf, p * cur1.y);
        acc1.z = fmaf(acc1.z, cf, p * cur1.z);
        acc1.w = fmaf(acc1.w, cf, p * cur1.w);

        cur0 = ncur0; cur1 = ncur1;
        j = jn;
    }

    // merge the 4 slot softmax states (stages: xor 8, xor 16; preserves c/head)
#pragma unroll
    for (int off = 8; off <= 16; off <<= 1) {
        float mo = __shfl_xor_sync(0xffffffffu, m, off);
        float nm = fmaxf(m, mo);
        float cf = __expf(m - nm);
        s *= cf;
        acc0.x *= cf; acc0.y *= cf; acc0.z *= cf; acc0.w *= cf;
        acc1.x *= cf; acc1.y *= cf; acc1.z *= cf; acc1.w *= cf;
        s += __shfl_xor_sync(0xffffffffu, s, off);
        acc0.x += __shfl_xor_sync(0xffffffffu, acc0.x, off);
        acc0.y += __shfl_xor_sync(0xffffffffu, acc0.y, off);
        acc0.z += __shfl_xor_sync(0xffffffffu, acc0.z, off);
        acc0.w += __shfl_xor_sync(0xffffffffu, acc0.w, off);
        acc1.x += __shfl_xor_sync(0xffffffffu, acc1.x, off);
        acc1.y += __shfl_xor_sync(0xffffffffu, acc1.y, off);
        acc1.z += __shfl_xor_sync(0xffffffffu, acc1.z, off);
        acc1.w += __shfl_xor_sync(0xffffffffu, acc1.w, off);
        m = nm;
    }

    if (lane < 8) {
        float inv = 1.f / s;
        float4 bv0 = ((const float4*)bias)[2 * c];
        float4 bv1 = ((const float4*)bias)[2 * c + 1];
        float4 o0, o1;
        o0.x = fmaf(acc0.x, inv, bv0.x);
        o0.y = fmaf(acc0.y, inv, bv0.y);
        o0.z = fmaf(acc0.z, inv, bv0.z);
        o0.w = fmaf(acc0.w, inv, bv0.w);
        o1.x = fmaf(acc1.x, inv, bv1.x);
        o1.y = fmaf(acc1.y, inv, bv1.y);
        o1.z = fmaf(acc1.z, inv, bv1.z);
        o1.w = fmaf(acc1.w, inv, bv1.w);
        // epilogue leaky_relu(0.01)
        o0.x = fmaxf(o0.x, 0.f) + 0.01f * fminf(o0.x, 0.f);
        o0.y = fmaxf(o0.y, 0.f) + 0.01f * fminf(o0.y, 0.f);
        o0.z = fmaxf(o0.z, 0.f) + 0.01f * fminf(o0.z, 0.f);
        o0.w = fmaxf(o0.w, 0.f) + 0.01f * fminf(o0.w, 0.f);
        o1.x = fmaxf(o1.x, 0.f) + 0.01f * fminf(o1.x, 0.f);
        o1.y = fmaxf(o1.y, 0.f) + 0.01f * fminf(o1.y, 0.f);
        o1.z = fmaxf(o1.z, 0.f) + 0.01f * fminf(o1.z, 0.f);
        o1.w = fmaxf(o1.w, 0.f) + 0.01f * fminf(o1.w, 0.f);
        float4* o4 = (float4*)(out + (size_t)node * 64);
        o4[2 * c]     = o0;
        o4[2 * c + 1] = o1;
    }
}

// ---------------- GATv2 edge kernel v3, H=1, C=10 (layer 2) -----------------
// 4 edges/iter: slot = lane>>3, c = lane&7; lane owns features {2c, 2c+1},
// active when c < 5. Single head -> full 8-lane reduction (xor 4,2,1) is
// correct (inactive lanes contribute 0 via av=0).
__global__ __launch_bounds__(256)
void gat_h1c10_kernel(const float* __restrict__ att,
                      const float* __restrict__ bias, int n)
{
    const float* __restrict__ xl = g_xl;
    float* __restrict__ out = g_h3;

    int node = (blockIdx.x * blockDim.x + threadIdx.x) >> 5;
    if (node >= n) return;
    int lane = threadIdx.x & 31;
    int c    = lane & 7;
    int slot = lane >> 3;
    bool act = c < 5;

    float2 xrv = make_float2(0.f, 0.f), av = make_float2(0.f, 0.f);
    if (act) {
        xrv = *(const float2*)(g_xr + (size_t)node * 10 + 2 * c);
        av  = *(const float2*)(att + 2 * c);
    }

    int j  = g_offsets[node];
    const int j1 = g_offsets[node + 1];

    float m = -1e30f, s = 0.f;
    float2 acc = make_float2(0.f, 0.f);

    int src = g_csr_src[j + slot];
    float2 cur = act ? *(const float2*)(xl + (size_t)src * 10 + 2 * c)
                     : make_float2(0.f, 0.f);

    while (j < j1) {
        int jn = j + 4;
        int nsrc = g_csr_src[jn + slot];
        float2 ncur = act ? *(const float2*)(xl + (size_t)nsrc * 10 + 2 * c)
                          : make_float2(0.f, 0.f);

        float t0 = cur.x + xrv.x;
        float t1 = cur.y + xrv.y;
        float v = fmaf(lrelu02(t0), av.x, lrelu02(t1) * av.y);
        v += __shfl_xor_sync(0xffffffffu, v, 4);
        v += __shfl_xor_sync(0xffffffffu, v, 2);
        v += __shfl_xor_sync(0xffffffffu, v, 1);
        if (j + slot >= j1) v = -2e30f;

        float d  = v - m;
        float e  = __expf(-fabsf(d));
        float cf = (d > 0.f) ? e : 1.f;
        float p  = (d > 0.f) ? 1.f : e;
        m = fmaxf(m, v);
        s = fmaf(s, cf, p);
        acc.x = fmaf(acc.x, cf, p * cur.x);
        acc.y = fmaf(acc.y, cf, p * cur.y);

        cur = ncur;
        j = jn;
    }

#pragma unroll
    for (int off = 8; off <= 16; off <<= 1) {
        float mo = __shfl_xor_sync(0xffffffffu, m, off);
        float nm = fmaxf(m, mo);
        float cf = __expf(m - nm);
        s *= cf;  acc.x *= cf;  acc.y *= cf;
        s += __shfl_xor_sync(0xffffffffu, s, off);
        acc.x += __shfl_xor_sync(0xffffffffu, acc.x, off);
        acc.y += __shfl_xor_sync(0xffffffffu, acc.y, off);
        m = nm;
    }

    if (lane < 8 && act) {
        float inv = 1.f / s;
        float2 bv = *(const float2*)(bias + 2 * c);
        *(float2*)(out + (size_t)node * 10 + 2 * c) =
            make_float2(fmaf(acc.x, inv, bv.x), fmaf(acc.y, inv, bv.y));
    }
}

// ---------------- pooling: block per graph ----------------------------------
__device__ __forceinline__ int lb_words(const int* a, int n, int key, int is64) {
    int lo = 0, hi = n;
    while (lo < hi) {
        int mid = (lo + hi) >> 1;
        int v = is64 ? a[2 * mid] : a[mid];
        if (v < key) lo = mid + 1; else hi = mid;
    }
    return lo;
}

__global__ __launch_bounds__(256)
void pool_kernel(const int* __restrict__ batch,
                 float* __restrict__ out, int n)
{
    const float* __restrict__ H = g_h3;
    __shared__ int sbeg, send;
    __shared__ float red[8][10];
    int g = blockIdx.x;
    int tid = threadIdx.x;
    int is64 = g_is64;
    if (tid == 0) sbeg = lb_words(batch, n, g, is64);
    if (tid == 1) send = lb_words(batch, n, g + 1, is64);
    __syncthreads();
    int beg = sbeg, end = send;

    float acc[10];
#pragma unroll
    for (int c = 0; c < 10; ++c) acc[c] = 0.f;
    for (int i = beg + tid; i < end; i += 256) {
#pragma unroll
        for (int c = 0; c < 10; ++c) acc[c] += H[(size_t)i * 10 + c];
    }
#pragma unroll
    for (int c = 0; c < 10; ++c) {
        acc[c] += __shfl_xor_sync(0xffffffffu, acc[c], 16);
        acc[c] += __shfl_xor_sync(0xffffffffu, acc[c], 8);
        acc[c] += __shfl_xor_sync(0xffffffffu, acc[c], 4);
        acc[c] += __shfl_xor_sync(0xffffffffu, acc[c], 2);
        acc[c] += __shfl_xor_sync(0xffffffffu, acc[c], 1);
    }
    int wid = tid >> 5, lane = tid & 31;
    if (lane == 0) {
#pragma unroll
        for (int c = 0; c < 10; ++c) red[wid][c] = acc[c];
    }
    __syncthreads();
    if (tid < 10) {
        float s = 0.f;
#pragma unroll
        for (int w = 0; w < 8; ++w) s += red[w][tid];
        float cnt = (float)(end - beg);
        if (cnt < 1.f) cnt = 1.f;
        out[g * 10 + tid] = s / cnt;
    }
}

// ---------------- launch -----------------------------------------------------
extern "C" void kernel_launch(void* const* d_in, const int* in_sizes, int n_in,
                              void* d_out, int out_size)
{
    const float* x     = (const float*)d_in[0];
    const int*   ei    = (const int*)d_in[1];    // int32 words (int64 handled via sniff)
    const int*   batch = (const int*)d_in[2];
    const float* Wl0 = (const float*)d_in[3];
    const float* bl0 = (const float*)d_in[4];
    const float* Wr0 = (const float*)d_in[5];
    const float* br0 = (const float*)d_in[6];
    const float* att0= (const float*)d_in[7];
    const float* b0  = (const float*)d_in[8];
    const float* Wl1 = (const float*)d_in[9];
    const float* bl1 = (const float*)d_in[10];
    const float* Wr1 = (const float*)d_in[11];
    const float* br1 = (const float*)d_in[12];
    const float* att1= (const float*)d_in[13];
    const float* b1  = (const float*)d_in[14];
    const float* Wl2 = (const float*)d_in[15];
    const float* bl2 = (const float*)d_in[16];
    const float* Wr2 = (const float*)d_in[17];
    const float* br2 = (const float*)d_in[18];
    const float* att2= (const float*)d_in[19];
    const float* b2  = (const float*)d_in[20];
    float* out = (float*)d_out;

    const int n = NN;

    // ---- CSR build: init+sniff, hist, single-pass scan, scatter ----
    init_kernel<<<(n + 255) / 256, 256>>>(ei, n);
    hist_kernel<<<(NE / 2 + 255) / 256, 256>>>(ei);
    scan_single_kernel<<<SBLOCKS, SCHUNK>>>(n);
    scatter_kernel<<<(NE / 2 + 255) / 256, 256>>>(ei);

    const int gemm_grid = (n + 127) / 128;
    const int gat_grid  = (n + 7) / 8;        // 8 warps/block

    // ---- layer 0 ----  (x -> xl, xr; gat -> h1(2))
    gemm_dual_tf32_kernel<128><<<gemm_grid, 256>>>(x, -1, Wl0, bl0, Wr0, br0, n);
    gat_h2c32_kernel<<<gat_grid, 256>>>(2, att0, b0, n);

    // ---- layer 1 ----  (h1(2) -> xl, xr; gat -> h2(3))
    gemm_dual_tf32_kernel<64><<<gemm_grid, 256>>>(nullptr, 2, Wl1, bl1, Wr1, br1, n);
    gat_h2c32_kernel<<<gat_grid, 256>>>(3, att1, b1, n);

    // ---- layer 2 ----  (h2(3) -> xl, xr; gat -> h3)
    gemm_small10_dual_kernel<<<gemm_grid, 128>>>(Wl2, bl2, Wr2, br2, n);
    gat_h1c10_kernel<<<gat_grid, 256>>>(att2, b2, n);

    // ---- pooling ----
    pool_kernel<<<NGRAPHS, 256>>>(batch, out, n);
}

// round 14
// speedup vs baseline: 1.3298x; 1.3298x over previous
#include <cuda_runtime.h>
#include <cuda_bf16.h>
#include <math_constants.h>
#include <cstdint>

// Problem constants (fixed by the dataset)
#define NN      50000
#define NE      1600000
#define NETOT   (NE + NN)      // edges + self loops
#define NGRAPHS 64

#define SCHUNK  512
#define SBLOCKS ((NN + SCHUNK - 1) / SCHUNK)   // 98

// ---------------- scratch (static device globals; no allocs allowed) --------
__device__ float g_xl[NN * 64];
__device__ float g_xr[NN * 64];
__device__ float g_h1[NN * 64];
__device__ float g_h2[NN * 64];
__device__ float g_h3[NN * 10];
__device__ int   g_counts[NN];
__device__ int   g_offsets[NN + 1];
__device__ int   g_cursor[NN];
__device__ int   g_csr_src[NETOT + 64];   // +pad: allows unconditional prefetch
__device__ int   g_bsum[SBLOCKS];
__device__ int   g_is64;   // 1 if index inputs are stored as int64 words

// Device-side scratch selector: ids 0=xl 1=xr 2=h1 3=h2 4=h3
__device__ __forceinline__ float* scratch(int id) {
    switch (id) {
        case 0: return g_xl;
        case 1: return g_xr;
        case 2: return g_h1;
        case 3: return g_h2;
        default: return g_h3;
    }
}

// ---------------- tf32 helpers ----------------------------------------------
__device__ __forceinline__ float tf32r(float x) {
    unsigned int u;
    asm("cvt.rna.tf32.f32 %0, %1;" : "=r"(u) : "f"(x));
    return __uint_as_float(u);
}

__device__ __forceinline__ void mma_tf32(float* c, const unsigned int* a,
                                         unsigned int b0, unsigned int b1) {
    asm volatile(
        "mma.sync.aligned.m16n8k8.row.col.f32.tf32.tf32.f32 "
        "{%0,%1,%2,%3}, {%4,%5,%6,%7}, {%8,%9}, {%0,%1,%2,%3};"
        : "+f"(c[0]), "+f"(c[1]), "+f"(c[2]), "+f"(c[3])
        : "r"(a[0]), "r"(a[1]), "r"(a[2]), "r"(a[3]), "r"(b0), "r"(b1));
}

__device__ __forceinline__ float lrelu02(float t) {
    return fmaxf(t, 0.f) + 0.2f * fminf(t, 0.f);
}

// ---------------- init: counts, pad, dtype sniff ----------------------------
__global__ void init_kernel(const int* __restrict__ w, int n) {
    int i = blockIdx.x * blockDim.x + threadIdx.x;
    if (i < n) g_counts[i] = 1;            // self loop pre-counted
    if (i < 64) g_csr_src[NETOT + i] = 0;  // safe pad for prefetch
    if (i == 0) {
        int acc = 0;
#pragma unroll
        for (int k = 1; k < 128; k += 2) acc |= w[k];
        g_is64 = (acc == 0) ? 1 : 0;
    }
}

// ---------------- hist: 2 edges per thread ----------------------------------
__global__ void hist_kernel(const int* __restrict__ ei) {
    int t = blockIdx.x * blockDim.x + threadIdx.x;
    if (t < NE / 2) {
        int d0, d1;
        if (g_is64) {
            int4 v = ((const int4*)ei)[(NE / 2) + t];  // dst words of edges 2t,2t+1
            d0 = v.x; d1 = v.z;
        } else {
            int2 v = ((const int2*)ei)[(NE / 2) + t];
            d0 = v.x; d1 = v.y;
        }
        if ((unsigned)d0 < (unsigned)NN) atomicAdd(&g_counts[d0], 1);
        if ((unsigned)d1 < (unsigned)NN) atomicAdd(&g_counts[d1], 1);
    }
}

// ---- 3-stage multi-block exclusive scan of g_counts -> g_offsets/g_cursor --
__global__ __launch_bounds__(SCHUNK)
void scan_reduce_kernel(int n) {
    __shared__ int warp_s[SCHUNK / 32];
    int b = blockIdx.x, tid = threadIdx.x;
    int i = b * SCHUNK + tid;
    int v = (i < n) ? g_counts[i] : 0;
#pragma unroll
    for (int o = 16; o; o >>= 1) v += __shfl_xor_sync(0xffffffffu, v, o);
    if ((tid & 31) == 0) warp_s[tid >> 5] = v;
    __syncthreads();
    if (tid < (SCHUNK / 32)) {
        int s = warp_s[tid];
#pragma unroll
        for (int o = (SCHUNK / 64); o; o >>= 1)
            s += __shfl_xor_sync(0xffffffffu, s, o);
        if (tid == 0) g_bsum[b] = s;
    }
}

__global__ __launch_bounds__(128)
void scan_bsum_kernel() {
    __shared__ int sh[128];
    int tid = threadIdx.x;
    int v = (tid < SBLOCKS) ? g_bsum[tid] : 0;
    sh[tid] = v;
    __syncthreads();
#pragma unroll
    for (int o = 1; o < 128; o <<= 1) {
        int t = (tid >= o) ? sh[tid - o] : 0;
        __syncthreads();
        sh[tid] += t;
        __syncthreads();
    }
    if (tid < SBLOCKS) g_bsum[tid] = sh[tid] - v;   // exclusive
    if (tid == 127) g_offsets[NN] = sh[127];        // total
}

// scan_apply also PLACES THE SELF-LOOP at the segment head and starts the
// cursor past it — scatter then only handles real edges (saves 50k atomics).
__global__ __launch_bounds__(SCHUNK)
void scan_apply_kernel(int n) {
    __shared__ int sh[SCHUNK];
    int b = blockIdx.x, tid = threadIdx.x;
    int i = b * SCHUNK + tid;
    int v = (i < n) ? g_counts[i] : 0;
    sh[tid] = v;
    __syncthreads();
#pragma unroll
    for (int o = 1; o < SCHUNK; o <<= 1) {
        int t = (tid >= o) ? sh[tid - o] : 0;
        __syncthreads();
        sh[tid] += t;
        __syncthreads();
    }
    if (i < n) {
        int excl = g_bsum[b] + sh[tid] - v;
        g_offsets[i] = excl;
        g_csr_src[excl] = i;        // self loop at segment head
        g_cursor[i]  = excl + 1;
    }
}

// ---------------- scatter: 2 edges per thread --------------------------------
__global__ void scatter_kernel(const int* __restrict__ ei) {
    int t = blockIdx.x * blockDim.x + threadIdx.x;
    if (t < NE / 2) {
        int s0, s1, d0, d1;
        if (g_is64) {
            int4 sv = ((const int4*)ei)[t];             // src words of edges 2t,2t+1
            int4 dv = ((const int4*)ei)[(NE / 2) + t];  // dst words
            s0 = sv.x; s1 = sv.z;
            d0 = dv.x; d1 = dv.z;
        } else {
            int2 sv = ((const int2*)ei)[t];
            int2 dv = ((const int2*)ei)[(NE / 2) + t];
            s0 = sv.x; s1 = sv.y;
            d0 = dv.x; d1 = dv.y;
        }
        if ((unsigned)d0 < (unsigned)NN && (unsigned)s0 < (unsigned)NN) {
            int pos = atomicAdd(&g_cursor[d0], 1);
            g_csr_src[pos] = s0;
        }
        if ((unsigned)d1 < (unsigned)NN && (unsigned)s1 < (unsigned)NN) {
            int pos = atomicAdd(&g_cursor[d1], 1);
            g_csr_src[pos] = s1;
        }
    }
}

// ---------------- dual GEMM via tf32 tensor cores ---------------------------
// Yl = X@Wl+Bl, Yr = X@Wr+Br (OC=64 each). Output treated as concat 128 cols.
// CTA: 256 thr = 8 warps; warp w -> rows (w&3)*32..+31, cols (w>>2)*64..+63.
template<int K>
__global__ __launch_bounds__(256)
void gemm_dual_tf32_kernel(const float* __restrict__ Xext, int xid,
                           const float* __restrict__ Wl, const float* __restrict__ Bl,
                           const float* __restrict__ Wr, const float* __restrict__ Br,
                           int n)
{
    const float* __restrict__ X = Xext ? Xext : scratch(xid);

    __shared__ float sX[16][136];   // [k][row], stride 136 -> conflict-free frags
    __shared__ float sW[16][136];   // [k][col] concat (0..63 Wl, 64..127 Wr)

    int tid  = threadIdx.x;
    int lane = tid & 31;
    int w    = tid >> 5;
    int gid  = lane >> 2;     // 0..7
    int tig  = lane & 3;      // 0..3
    int rbase = (w & 3) * 32;
    int cbase = (w >> 2) * 64;
    int row0  = blockIdx.x * 128;

    float c[2][8][4];
#pragma unroll
    for (int t = 0; t < 2; ++t)
#pragma unroll
        for (int nt = 0; nt < 8; ++nt)
#pragma unroll
            for (int q = 0; q < 4; ++q) c[t][nt][q] = 0.f;

    int srow = tid & 127;            // staging row 0..127
    int ksub = (tid >> 7) * 8;       // 0 or 8

    for (int kc = 0; kc < K; kc += 16) {
        // ---- global loads (no smem touched yet) ----
        float4 v0 = make_float4(0.f, 0.f, 0.f, 0.f);
        float4 v1 = make_float4(0.f, 0.f, 0.f, 0.f);
        int grow = row0 + srow;
        if (grow < n) {
            v0 = *(const float4*)(X + (size_t)grow * K + kc + ksub);
            v1 = *(const float4*)(X + (size_t)grow * K + kc + ksub + 4);
        }
        float4 wv[2]; int wk[2], wc4[2];
#pragma unroll
        for (int t = 0; t < 2; ++t) {
            int i = tid + t * 256;
            wk[t]  = i >> 5;
            wc4[t] = (i & 31) << 2;
            wv[t] = (wc4[t] < 64)
                  ? *(const float4*)(Wl + (size_t)(kc + wk[t]) * 64 + wc4[t])
                  : *(const float4*)(Wr + (size_t)(kc + wk[t]) * 64 + (wc4[t] - 64));
        }
        __syncthreads();   // prior compute done before overwriting smem
        // ---- stage with tf32 rounding ----
        sX[ksub + 0][srow] = tf32r(v0.x);
        sX[ksub + 1][srow] = tf32r(v0.y);
        sX[ksub + 2][srow] = tf32r(v0.z);
        sX[ksub + 3][srow] = tf32r(v0.w);
        sX[ksub + 4][srow] = tf32r(v1.x);
        sX[ksub + 5][srow] = tf32r(v1.y);
        sX[ksub + 6][srow] = tf32r(v1.z);
        sX[ksub + 7][srow] = tf32r(v1.w);
#pragma unroll
        for (int t = 0; t < 2; ++t) {
            sW[wk[t]][wc4[t] + 0] = tf32r(wv[t].x);
            sW[wk[t]][wc4[t] + 1] = tf32r(wv[t].y);
            sW[wk[t]][wc4[t] + 2] = tf32r(wv[t].z);
            sW[wk[t]][wc4[t] + 3] = tf32r(wv[t].w);
        }
        __syncthreads();
        // ---- compute 2 k8 sub-blocks ----
#pragma unroll
        for (int k8 = 0; k8 < 16; k8 += 8) {
            unsigned int a[2][4];
#pragma unroll
            for (int t = 0; t < 2; ++t) {
                int r = rbase + t * 16;
                a[t][0] = __float_as_uint(sX[k8 + tig][r + gid]);
                a[t][1] = __float_as_uint(sX[k8 + tig][r + gid + 8]);
                a[t][2] = __float_as_uint(sX[k8 + tig + 4][r + gid]);
                a[t][3] = __float_as_uint(sX[k8 + tig + 4][r + gid + 8]);
            }
#pragma unroll
            for (int nt = 0; nt < 8; ++nt) {
                unsigned int b0 = __float_as_uint(sW[k8 + tig][cbase + nt * 8 + gid]);
                unsigned int b1 = __float_as_uint(sW[k8 + tig + 4][cbase + nt * 8 + gid]);
                mma_tf32(c[0][nt], a[0], b0, b1);
                mma_tf32(c[1][nt], a[1], b0, b1);
            }
        }
    }

    // ---- epilogue: bias + split into Yl/Yr ----
#pragma unroll
    for (int nt = 0; nt < 8; ++nt) {
        int col = cbase + nt * 8 + tig * 2;
        bool isR = col >= 64;
        int lc = isR ? (col - 64) : col;
        float* __restrict__ Y = isR ? g_xr : g_xl;
        const float* __restrict__ Bb = isR ? Br : Bl;
        float bx = __ldg(Bb + lc);
        float by = __ldg(Bb + lc + 1);
#pragma unroll
        for (int t = 0; t < 2; ++t) {
            int r0 = row0 + rbase + t * 16 + gid;
            if (r0 < n) {
                *(float2*)(Y + (size_t)r0 * 64 + lc) =
                    make_float2(c[t][nt][0] + bx, c[t][nt][1] + by);
            }
            int r1 = r0 + 8;
            if (r1 < n) {
                *(float2*)(Y + (size_t)r1 * 64 + lc) =
                    make_float2(c[t][nt][2] + bx, c[t][nt][3] + by);
            }
        }
    }
}

// dual small GEMM: Yl = X@Wl+Bl, Yr = X@Wr+Br, OC=10, K=64. X = g_h2.
__global__ __launch_bounds__(128)
void gemm_small10_dual_kernel(const float* __restrict__ Wl, const float* __restrict__ Bl,
                              const float* __restrict__ Wr, const float* __restrict__ Br,
                              int n)
{
    const float* __restrict__ X = g_h2;
    float* __restrict__ Yl = g_xl;
    float* __restrict__ Yr = g_xr;

    __shared__ float sWl[64][10];
    __shared__ float sWr[64][10];
    __shared__ float sX[128][65];
    int tid = threadIdx.x;
    for (int i = tid; i < 640; i += 128) {
        sWl[i / 10][i % 10] = Wl[i];
        sWr[i / 10][i % 10] = Wr[i];
    }
    int row0 = blockIdx.x * 128;
    for (int i = tid; i < 2048; i += 128) {
        int r = i >> 4, c4 = (i & 15) << 2;
        int gr = row0 + r;
        float4 v = make_float4(0.f, 0.f, 0.f, 0.f);
        if (gr < n) v = *(const float4*)(X + (size_t)gr * 64 + c4);
        sX[r][c4 + 0] = v.x; sX[r][c4 + 1] = v.y;
        sX[r][c4 + 2] = v.z; sX[r][c4 + 3] = v.w;
    }
    __syncthreads();
    int row = row0 + tid;
    float accl[10], accr[10];
#pragma unroll
    for (int c = 0; c < 10; ++c) { accl[c] = 0.f; accr[c] = 0.f; }
#pragma unroll 4
    for (int k = 0; k < 64; ++k) {
        float a = sX[tid][k];
#pragma unroll
        for (int c = 0; c < 10; ++c) {
            accl[c] = fmaf(a, sWl[k][c], accl[c]);
            accr[c] = fmaf(a, sWr[k][c], accr[c]);
        }
    }
    if (row < n) {
#pragma unroll
        for (int c = 0; c < 10; ++c) {
            Yl[(size_t)row * 10 + c] = accl[c] + Bl[c];
            Yr[(size_t)row * 10 + c] = accr[c] + Br[c];
        }
    }
}

// ---------------- GATv2 edge kernel v3, H=2, C=32 ---------------------------
// Warp per node, 4 edges per iteration: slot = lane>>3 (edge), c = lane&7
// (feature chunk: floats [8c, 8c+8) = two float4s). Head 0 = lanes c 0..3,
// head 1 = lanes c 4..7 -> logit reduction is xor 2, xor 1 ONLY (per-head).
// Branchless online softmax per (slot, head); slots merged via xor 8, xor 16
// (flips slot bits only, so merges stay head-consistent).
__global__ __launch_bounds__(256)
void gat_h2c32_kernel(int oid, const float* __restrict__ att,
                      const float* __restrict__ bias, int n)
{
    const float4* __restrict__ xl4 = (const float4*)g_xl;
    float* __restrict__ out = scratch(oid);

    int node = (blockIdx.x * blockDim.x + threadIdx.x) >> 5;
    if (node >= n) return;
    int lane = threadIdx.x & 31;
    int c    = lane & 7;      // chunk pair id (0..7); head = c>>2
    int slot = lane >> 3;     // 0..3

    const float4* xr4 = (const float4*)(g_xr + (size_t)node * 64);
    float4 xrv0 = xr4[2 * c], xrv1 = xr4[2 * c + 1];
    float4 av0 = ((const float4*)att)[2 * c];
    float4 av1 = ((const float4*)att)[2 * c + 1];

    int j  = g_offsets[node];
    const int j1 = g_offsets[node + 1];

    float m = -1e30f, s = 0.f;
    float4 acc0 = make_float4(0.f, 0.f, 0.f, 0.f);
    float4 acc1 = make_float4(0.f, 0.f, 0.f, 0.f);

    int src = g_csr_src[j + slot];
    float4 cur0 = xl4[(size_t)src * 16 + 2 * c];
    float4 cur1 = xl4[(size_t)src * 16 + 2 * c + 1];

    while (j < j1) {
        int jn = j + 4;
        int nsrc = g_csr_src[jn + slot];                   // padded: always safe
        float4 ncur0 = xl4[(size_t)nsrc * 16 + 2 * c];     // prefetch next gather
        float4 ncur1 = xl4[(size_t)nsrc * 16 + 2 * c + 1];

        float v;
        {
            float t;
            t = cur0.x + xrv0.x; v  = lrelu02(t) * av0.x;
            t = cur0.y + xrv0.y; v  = fmaf(lrelu02(t), av0.y, v);
            t = cur0.z + xrv0.z; v  = fmaf(lrelu02(t), av0.z, v);
            t = cur0.w + xrv0.w; v  = fmaf(lrelu02(t), av0.w, v);
            t = cur1.x + xrv1.x; v  = fmaf(lrelu02(t), av1.x, v);
            t = cur1.y + xrv1.y; v  = fmaf(lrelu02(t), av1.y, v);
            t = cur1.z + xrv1.z; v  = fmaf(lrelu02(t), av1.z, v);
            t = cur1.w + xrv1.w; v  = fmaf(lrelu02(t), av1.w, v);
        }
        // per-head reduction: heads occupy 4-lane groups -> xor 2, xor 1 only
        v += __shfl_xor_sync(0xffffffffu, v, 2);
        v += __shfl_xor_sync(0xffffffffu, v, 1);
        if (j + slot >= j1) v = -2e30f;    // ragged-tail sentinel: zero contribution

        float d  = v - m;
        float e  = __expf(-fabsf(d));
        float cf = (d > 0.f) ? e : 1.f;
        float p  = (d > 0.f) ? 1.f : e;
        m = fmaxf(m, v);
        s = fmaf(s, cf, p);
        acc0.x = fmaf(acc0.x, cf, p * cur0.x);
        acc0.y = fmaf(acc0.y, cf, p * cur0.y);
        acc0.z = fmaf(acc0.z, cf, p * cur0.z);
        acc0.w = fmaf(acc0.w, cf, p * cur0.w);
        acc1.x = fmaf(acc1.x, cf, p * cur1.x);
        acc1.y = fmaf(acc1.y, cf, p * cur1.y);
        acc1.z = fmaf(acc1.z, cf, p * cur1.z);
        acc1.w = fmaf(acc1.w, cf, p * cur1.w);

        cur0 = ncur0; cur1 = ncur1;
        j = jn;
    }

    // merge the 4 slot softmax states (stages: xor 8, xor 16; preserves c/head)
#pragma unroll
    for (int off = 8; off <= 16; off <<= 1) {
        float mo = __shfl_xor_sync(0xffffffffu, m, off);
        float nm = fmaxf(m, mo);
        float cf = __expf(m - nm);
        s *= cf;
        acc0.x *= cf; acc0.y *= cf; acc0.z *= cf; acc0.w *= cf;
        acc1.x *= cf; acc1.y *= cf; acc1.z *= cf; acc1.w *= cf;
        s += __shfl_xor_sync(0xffffffffu, s, off);
        acc0.x += __shfl_xor_sync(0xffffffffu, acc0.x, off);
        acc0.y += __shfl_xor_sync(0xffffffffu, acc0.y, off);
        acc0.z += __shfl_xor_sync(0xffffffffu, acc0.z, off);
        acc0.w += __shfl_xor_sync(0xffffffffu, acc0.w, off);
        acc1.x += __shfl_xor_sync(0xffffffffu, acc1.x, off);
        acc1.y += __shfl_xor_sync(0xffffffffu, acc1.y, off);
        acc1.z += __shfl_xor_sync(0xffffffffu, acc1.z, off);
        acc1.w += __shfl_xor_sync(0xffffffffu, acc1.w, off);
        m = nm;
    }

    if (lane < 8) {
        float inv = 1.f / s;
        float4 bv0 = ((const float4*)bias)[2 * c];
        float4 bv1 = ((const float4*)bias)[2 * c + 1];
        float4 o0, o1;
        o0.x = fmaf(acc0.x, inv, bv0.x);
        o0.y = fmaf(acc0.y, inv, bv0.y);
        o0.z = fmaf(acc0.z, inv, bv0.z);
        o0.w = fmaf(acc0.w, inv, bv0.w);
        o1.x = fmaf(acc1.x, inv, bv1.x);
        o1.y = fmaf(acc1.y, inv, bv1.y);
        o1.z = fmaf(acc1.z, inv, bv1.z);
        o1.w = fmaf(acc1.w, inv, bv1.w);
        // epilogue leaky_relu(0.01)
        o0.x = fmaxf(o0.x, 0.f) + 0.01f * fminf(o0.x, 0.f);
        o0.y = fmaxf(o0.y, 0.f) + 0.01f * fminf(o0.y, 0.f);
        o0.z = fmaxf(o0.z, 0.f) + 0.01f * fminf(o0.z, 0.f);
        o0.w = fmaxf(o0.w, 0.f) + 0.01f * fminf(o0.w, 0.f);
        o1.x = fmaxf(o1.x, 0.f) + 0.01f * fminf(o1.x, 0.f);
        o1.y = fmaxf(o1.y, 0.f) + 0.01f * fminf(o1.y, 0.f);
        o1.z = fmaxf(o1.z, 0.f) + 0.01f * fminf(o1.z, 0.f);
        o1.w = fmaxf(o1.w, 0.f) + 0.01f * fminf(o1.w, 0.f);
        float4* o4 = (float4*)(out + (size_t)node * 64);
        o4[2 * c]     = o0;
        o4[2 * c + 1] = o1;
    }
}

// ---------------- GATv2 edge kernel v3, H=1, C=10 (layer 2) -----------------
// 4 edges/iter: slot = lane>>3, c = lane&7; lane owns features {2c, 2c+1},
// active when c < 5. Single head -> full 8-lane reduction (xor 4,2,1) is
// correct (inactive lanes contribute 0 via av=0).
__global__ __launch_bounds__(256)
void gat_h1c10_kernel(const float* __restrict__ att,
                      const float* __restrict__ bias, int n)
{
    const float* __restrict__ xl = g_xl;
    float* __restrict__ out = g_h3;

    int node = (blockIdx.x * blockDim.x + threadIdx.x) >> 5;
    if (node >= n) return;
    int lane = threadIdx.x & 31;
    int c    = lane & 7;
    int slot = lane >> 3;
    bool act = c < 5;

    float2 xrv = make_float2(0.f, 0.f), av = make_float2(0.f, 0.f);
    if (act) {
        xrv = *(const float2*)(g_xr + (size_t)node * 10 + 2 * c);
        av  = *(const float2*)(att + 2 * c);
    }

    int j  = g_offsets[node];
    const int j1 = g_offsets[node + 1];

    float m = -1e30f, s = 0.f;
    float2 acc = make_float2(0.f, 0.f);

    int src = g_csr_src[j + slot];
    float2 cur = act ? *(const float2*)(xl + (size_t)src * 10 + 2 * c)
                     : make_float2(0.f, 0.f);

    while (j < j1) {
        int jn = j + 4;
        int nsrc = g_csr_src[jn + slot];
        float2 ncur = act ? *(const float2*)(xl + (size_t)nsrc * 10 + 2 * c)
                          : make_float2(0.f, 0.f);

        float t0 = cur.x + xrv.x;
        float t1 = cur.y + xrv.y;
        float v = fmaf(lrelu02(t0), av.x, lrelu02(t1) * av.y);
        v += __shfl_xor_sync(0xffffffffu, v, 4);
        v += __shfl_xor_sync(0xffffffffu, v, 2);
        v += __shfl_xor_sync(0xffffffffu, v, 1);
        if (j + slot >= j1) v = -2e30f;

        float d  = v - m;
        float e  = __expf(-fabsf(d));
        float cf = (d > 0.f) ? e : 1.f;
        float p  = (d > 0.f) ? 1.f : e;
        m = fmaxf(m, v);
        s = fmaf(s, cf, p);
        acc.x = fmaf(acc.x, cf, p * cur.x);
        acc.y = fmaf(acc.y, cf, p * cur.y);

        cur = ncur;
        j = jn;
    }

#pragma unroll
    for (int off = 8; off <= 16; off <<= 1) {
        float mo = __shfl_xor_sync(0xffffffffu, m, off);
        float nm = fmaxf(m, mo);
        float cf = __expf(m - nm);
        s *= cf;  acc.x *= cf;  acc.y *= cf;
        s += __shfl_xor_sync(0xffffffffu, s, off);
        acc.x += __shfl_xor_sync(0xffffffffu, acc.x, off);
        acc.y += __shfl_xor_sync(0xffffffffu, acc.y, off);
        m = nm;
    }

    if (lane < 8 && act) {
        float inv = 1.f / s;
        float2 bv = *(const float2*)(bias + 2 * c);
        *(float2*)(out + (size_t)node * 10 + 2 * c) =
            make_float2(fmaf(acc.x, inv, bv.x), fmaf(acc.y, inv, bv.y));
    }
}

// ---------------- pooling: block per graph ----------------------------------
__device__ __forceinline__ int lb_words(const int* a, int n, int key, int is64) {
    int lo = 0, hi = n;
    while (lo < hi) {
        int mid = (lo + hi) >> 1;
        int v = is64 ? a[2 * mid] : a[mid];
        if (v < key) lo = mid + 1; else hi = mid;
    }
    return lo;
}

__global__ __launch_bounds__(256)
void pool_kernel(const int* __restrict__ batch,
                 float* __restrict__ out, int n)
{
    const float* __restrict__ H = g_h3;
    __shared__ int sbeg, send;
    __shared__ float red[8][10];
    int g = blockIdx.x;
    int tid = threadIdx.x;
    int is64 = g_is64;
    if (tid == 0) sbeg = lb_words(batch, n, g, is64);
    if (tid == 1) send = lb_words(batch, n, g + 1, is64);
    __syncthreads();
    int beg = sbeg, end = send;

    float acc[10];
#pragma unroll
    for (int c = 0; c < 10; ++c) acc[c] = 0.f;
    for (int i = beg + tid; i < end; i += 256) {
#pragma unroll
        for (int c = 0; c < 10; ++c) acc[c] += H[(size_t)i * 10 + c];
    }
#pragma unroll
    for (int c = 0; c < 10; ++c) {
        acc[c] += __shfl_xor_sync(0xffffffffu, acc[c], 16);
        acc[c] += __shfl_xor_sync(0xffffffffu, acc[c], 8);
        acc[c] += __shfl_xor_sync(0xffffffffu, acc[c], 4);
        acc[c] += __shfl_xor_sync(0xffffffffu, acc[c], 2);
        acc[c] += __shfl_xor_sync(0xffffffffu, acc[c], 1);
    }
    int wid = tid >> 5, lane = tid & 31;
    if (lane == 0) {
#pragma unroll
        for (int c = 0; c < 10; ++c) red[wid][c] = acc[c];
    }
    __syncthreads();
    if (tid < 10) {
        float s = 0.f;
#pragma unroll
        for (int w = 0; w < 8; ++w) s += red[w][tid];
        float cnt = (float)(end - beg);
        if (cnt < 1.f) cnt = 1.f;
        out[g * 10 + tid] = s / cnt;
    }
}

// ---------------- launch -----------------------------------------------------
extern "C" void kernel_launch(void* const* d_in, const int* in_sizes, int n_in,
                              void* d_out, int out_size)
{
    const float* x     = (const float*)d_in[0];
    const int*   ei    = (const int*)d_in[1];    // int32 words (int64 handled via sniff)
    const int*   batch = (const int*)d_in[2];
    const float* Wl0 = (const float*)d_in[3];
    const float* bl0 = (const float*)d_in[4];
    const float* Wr0 = (const float*)d_in[5];
    const float* br0 = (const float*)d_in[6];
    const float* att0= (const float*)d_in[7];
    const float* b0  = (const float*)d_in[8];
    const float* Wl1 = (const float*)d_in[9];
    const float* bl1 = (const float*)d_in[10];
    const float* Wr1 = (const float*)d_in[11];
    const float* br1 = (const float*)d_in[12];
    const float* att1= (const float*)d_in[13];
    const float* b1  = (const float*)d_in[14];
    const float* Wl2 = (const float*)d_in[15];
    const float* bl2 = (const float*)d_in[16];
    const float* Wr2 = (const float*)d_in[17];
    const float* br2 = (const float*)d_in[18];
    const float* att2= (const float*)d_in[19];
    const float* b2  = (const float*)d_in[20];
    float* out = (float*)d_out;

    const int n = NN;

    // ---- CSR build: init+sniff, hist(2x), 3-kernel scan, scatter(2x) ----
    init_kernel<<<(n + 255) / 256, 256>>>(ei, n);
    hist_kernel<<<(NE / 2 + 255) / 256, 256>>>(ei);
    scan_reduce_kernel<<<SBLOCKS, SCHUNK>>>(n);
    scan_bsum_kernel<<<1, 128>>>();
    scan_apply_kernel<<<SBLOCKS, SCHUNK>>>(n);
    scatter_kernel<<<(NE / 2 + 255) / 256, 256>>>(ei);

    const int gemm_grid = (n + 127) / 128;
    const int gat_grid  = (n + 7) / 8;        // 8 warps/block

    // ---- layer 0 ----  (x -> xl, xr; gat -> h1(2))
    gemm_dual_tf32_kernel<128><<<gemm_grid, 256>>>(x, -1, Wl0, bl0, Wr0, br0, n);
    gat_h2c32_kernel<<<gat_grid, 256>>>(2, att0, b0, n);

    // ---- layer 1 ----  (h1(2) -> xl, xr; gat -> h2(3))
    gemm_dual_tf32_kernel<64><<<gemm_grid, 256>>>(nullptr, 2, Wl1, bl1, Wr1, br1, n);
    gat_h2c32_kernel<<<gat_grid, 256>>>(3, att1, b1, n);

    // ---- layer 2 ----  (h2(3) -> xl, xr; gat -> h3)
    gemm_small10_dual_kernel<<<gemm_grid, 128>>>(Wl2, bl2, Wr2, br2, n);
    gat_h1c10_kernel<<<gat_grid, 256>>>(att2, b2, n);

    // ---- pooling ----
    pool_kernel<<<NGRAPHS, 256>>>(batch, out, n);
}

// round 15
// speedup vs baseline: 1.3337x; 1.0029x over previous
#include <cuda_runtime.h>
#include <cuda_bf16.h>
#include <math_constants.h>
#include <cstdint>

// Problem constants (fixed by the dataset)
#define NN      50000
#define NE      1600000
#define NETOT   (NE + NN)      // edges + self loops
#define NGRAPHS 64

#define SCHUNK  512
#define SBLOCKS ((NN + SCHUNK - 1) / SCHUNK)   // 98

// ---------------- scratch (static device globals; no allocs allowed) --------
__device__ float g_xl[NN * 64];
__device__ float g_xr[NN * 64];
__device__ float g_h1[NN * 64];
__device__ float g_h2[NN * 64];
__device__ float g_h3[NN * 10];
__device__ int   g_counts[NN];
__device__ int   g_offsets[NN + 1];
__device__ int   g_cursor[NN];
__device__ int   g_csr_src[NETOT + 64];   // +pad: allows unconditional prefetch
__device__ int   g_bsum[SBLOCKS];
__device__ int   g_is64;   // 1 if index inputs are stored as int64 words

// Device-side scratch selector: ids 0=xl 1=xr 2=h1 3=h2 4=h3
__device__ __forceinline__ float* scratch(int id) {
    switch (id) {
        case 0: return g_xl;
        case 1: return g_xr;
        case 2: return g_h1;
        case 3: return g_h2;
        default: return g_h3;
    }
}

// ---------------- tf32 helpers ----------------------------------------------
__device__ __forceinline__ float tf32r(float x) {
    unsigned int u;
    asm("cvt.rna.tf32.f32 %0, %1;" : "=r"(u) : "f"(x));
    return __uint_as_float(u);
}

__device__ __forceinline__ void mma_tf32(float* c, const unsigned int* a,
                                         unsigned int b0, unsigned int b1) {
    asm volatile(
        "mma.sync.aligned.m16n8k8.row.col.f32.tf32.tf32.f32 "
        "{%0,%1,%2,%3}, {%4,%5,%6,%7}, {%8,%9}, {%0,%1,%2,%3};"
        : "+f"(c[0]), "+f"(c[1]), "+f"(c[2]), "+f"(c[3])
        : "r"(a[0]), "r"(a[1]), "r"(a[2]), "r"(a[3]), "r"(b0), "r"(b1));
}

__device__ __forceinline__ float lrelu02(float t) {
    return fmaxf(t, 0.f) + 0.2f * fminf(t, 0.f);
}

// ---------------- init: counts, pad, dtype sniff ----------------------------
__global__ void init_kernel(const int* __restrict__ w, int n) {
    int i = blockIdx.x * blockDim.x + threadIdx.x;
    if (i < n) g_counts[i] = 1;            // self loop pre-counted
    if (i < 64) g_csr_src[NETOT + i] = 0;  // safe pad for prefetch
    if (i == 0) {
        int acc = 0;
#pragma unroll
        for (int k = 1; k < 128; k += 2) acc |= w[k];
        g_is64 = (acc == 0) ? 1 : 0;
    }
}

// ---------------- hist: 2 edges per thread ----------------------------------
__global__ void hist_kernel(const int* __restrict__ ei) {
    int t = blockIdx.x * blockDim.x + threadIdx.x;
    if (t < NE / 2) {
        int d0, d1;
        if (g_is64) {
            int4 v = ((const int4*)ei)[(NE / 2) + t];  // dst words of edges 2t,2t+1
            d0 = v.x; d1 = v.z;
        } else {
            int2 v = ((const int2*)ei)[(NE / 2) + t];
            d0 = v.x; d1 = v.y;
        }
        if ((unsigned)d0 < (unsigned)NN) atomicAdd(&g_counts[d0], 1);
        if ((unsigned)d1 < (unsigned)NN) atomicAdd(&g_counts[d1], 1);
    }
}

// ---- 2-stage scan: reduce -> apply (apply re-scans bsum redundantly) -------
__global__ __launch_bounds__(SCHUNK)
void scan_reduce_kernel(int n) {
    __shared__ int warp_s[SCHUNK / 32];
    int b = blockIdx.x, tid = threadIdx.x;
    int i = b * SCHUNK + tid;
    int v = (i < n) ? g_counts[i] : 0;
#pragma unroll
    for (int o = 16; o; o >>= 1) v += __shfl_xor_sync(0xffffffffu, v, o);
    if ((tid & 31) == 0) warp_s[tid >> 5] = v;
    __syncthreads();
    if (tid < (SCHUNK / 32)) {
        int s = warp_s[tid];
#pragma unroll
        for (int o = (SCHUNK / 64); o; o >>= 1)
            s += __shfl_xor_sync(0xffffffffu, s, o);
        if (tid == 0) g_bsum[b] = s;
    }
}

// scan_apply: each block redundantly scans the 98-entry bsum array (cheap,
// fully parallel across blocks) -> no separate scan_bsum kernel needed.
// Also PLACES THE SELF-LOOP at the segment head and starts the cursor past
// it — scatter then only handles real edges (saves 50k atomics).
__global__ __launch_bounds__(SCHUNK)
void scan_apply_kernel(int n) {
    __shared__ int sh[SCHUNK];
    __shared__ int sb[128];
    int b = blockIdx.x, tid = threadIdx.x;

    // redundant inclusive scan of block sums
    if (tid < 128) sb[tid] = (tid < SBLOCKS) ? g_bsum[tid] : 0;
    __syncthreads();
#pragma unroll
    for (int o = 1; o < 128; o <<= 1) {
        int t = (tid >= o && tid < 128) ? sb[tid - o] : 0;
        __syncthreads();
        if (tid < 128) sb[tid] += t;
        __syncthreads();
    }
    int base = (b == 0) ? 0 : sb[b - 1];
    if (b == SBLOCKS - 1 && tid == 0) g_offsets[NN] = sb[SBLOCKS - 1];

    // per-element scan within the block
    int i = b * SCHUNK + tid;
    int v = (i < n) ? g_counts[i] : 0;
    sh[tid] = v;
    __syncthreads();
#pragma unroll
    for (int o = 1; o < SCHUNK; o <<= 1) {
        int t = (tid >= o) ? sh[tid - o] : 0;
        __syncthreads();
        sh[tid] += t;
        __syncthreads();
    }
    if (i < n) {
        int excl = base + sh[tid] - v;
        g_offsets[i] = excl;
        g_csr_src[excl] = i;        // self loop at segment head
        g_cursor[i]  = excl + 1;
    }
}

// ---------------- scatter: 2 edges per thread --------------------------------
__global__ void scatter_kernel(const int* __restrict__ ei) {
    int t = blockIdx.x * blockDim.x + threadIdx.x;
    if (t < NE / 2) {
        int s0, s1, d0, d1;
        if (g_is64) {
            int4 sv = ((const int4*)ei)[t];             // src words of edges 2t,2t+1
            int4 dv = ((const int4*)ei)[(NE / 2) + t];  // dst words
            s0 = sv.x; s1 = sv.z;
            d0 = dv.x; d1 = dv.z;
        } else {
            int2 sv = ((const int2*)ei)[t];
            int2 dv = ((const int2*)ei)[(NE / 2) + t];
            s0 = sv.x; s1 = sv.y;
            d0 = dv.x; d1 = dv.y;
        }
        if ((unsigned)d0 < (unsigned)NN && (unsigned)s0 < (unsigned)NN) {
            int pos = atomicAdd(&g_cursor[d0], 1);
            g_csr_src[pos] = s0;
        }
        if ((unsigned)d1 < (unsigned)NN && (unsigned)s1 < (unsigned)NN) {
            int pos = atomicAdd(&g_cursor[d1], 1);
            g_csr_src[pos] = s1;
        }
    }
}

// ---------------- dual GEMM via tf32 tensor cores ---------------------------
// Yl = X@Wl+Bl, Yr = X@Wr+Br (OC=64 each). Output treated as concat 128 cols.
// CTA: 256 thr = 8 warps; warp w -> rows (w&3)*32..+31, cols (w>>2)*64..+63.
template<int K>
__global__ __launch_bounds__(256)
void gemm_dual_tf32_kernel(const float* __restrict__ Xext, int xid,
                           const float* __restrict__ Wl, const float* __restrict__ Bl,
                           const float* __restrict__ Wr, const float* __restrict__ Br,
                           int n)
{
    const float* __restrict__ X = Xext ? Xext : scratch(xid);

    __shared__ float sX[16][136];   // [k][row], stride 136 -> conflict-free frags
    __shared__ float sW[16][136];   // [k][col] concat (0..63 Wl, 64..127 Wr)

    int tid  = threadIdx.x;
    int lane = tid & 31;
    int w    = tid >> 5;
    int gid  = lane >> 2;     // 0..7
    int tig  = lane & 3;      // 0..3
    int rbase = (w & 3) * 32;
    int cbase = (w >> 2) * 64;
    int row0  = blockIdx.x * 128;

    float c[2][8][4];
#pragma unroll
    for (int t = 0; t < 2; ++t)
#pragma unroll
        for (int nt = 0; nt < 8; ++nt)
#pragma unroll
            for (int q = 0; q < 4; ++q) c[t][nt][q] = 0.f;

    int srow = tid & 127;            // staging row 0..127
    int ksub = (tid >> 7) * 8;       // 0 or 8

    for (int kc = 0; kc < K; kc += 16) {
        // ---- global loads (no smem touched yet) ----
        float4 v0 = make_float4(0.f, 0.f, 0.f, 0.f);
        float4 v1 = make_float4(0.f, 0.f, 0.f, 0.f);
        int grow = row0 + srow;
        if (grow < n) {
            v0 = *(const float4*)(X + (size_t)grow * K + kc + ksub);
            v1 = *(const float4*)(X + (size_t)grow * K + kc + ksub + 4);
        }
        float4 wv[2]; int wk[2], wc4[2];
#pragma unroll
        for (int t = 0; t < 2; ++t) {
            int i = tid + t * 256;
            wk[t]  = i >> 5;
            wc4[t] = (i & 31) << 2;
            wv[t] = (wc4[t] < 64)
                  ? *(const float4*)(Wl + (size_t)(kc + wk[t]) * 64 + wc4[t])
                  : *(const float4*)(Wr + (size_t)(kc + wk[t]) * 64 + (wc4[t] - 64));
        }
        __syncthreads();   // prior compute done before overwriting smem
        // ---- stage with tf32 rounding ----
        sX[ksub + 0][srow] = tf32r(v0.x);
        sX[ksub + 1][srow] = tf32r(v0.y);
        sX[ksub + 2][srow] = tf32r(v0.z);
        sX[ksub + 3][srow] = tf32r(v0.w);
        sX[ksub + 4][srow] = tf32r(v1.x);
        sX[ksub + 5][srow] = tf32r(v1.y);
        sX[ksub + 6][srow] = tf32r(v1.z);
        sX[ksub + 7][srow] = tf32r(v1.w);
#pragma unroll
        for (int t = 0; t < 2; ++t) {
            sW[wk[t]][wc4[t] + 0] = tf32r(wv[t].x);
            sW[wk[t]][wc4[t] + 1] = tf32r(wv[t].y);
            sW[wk[t]][wc4[t] + 2] = tf32r(wv[t].z);
            sW[wk[t]][wc4[t] + 3] = tf32r(wv[t].w);
        }
        __syncthreads();
        // ---- compute 2 k8 sub-blocks ----
#pragma unroll
        for (int k8 = 0; k8 < 16; k8 += 8) {
            unsigned int a[2][4];
#pragma unroll
            for (int t = 0; t < 2; ++t) {
                int r = rbase + t * 16;
                a[t][0] = __float_as_uint(sX[k8 + tig][r + gid]);
                a[t][1] = __float_as_uint(sX[k8 + tig][r + gid + 8]);
                a[t][2] = __float_as_uint(sX[k8 + tig + 4][r + gid]);
                a[t][3] = __float_as_uint(sX[k8 + tig + 4][r + gid + 8]);
            }
#pragma unroll
            for (int nt = 0; nt < 8; ++nt) {
                unsigned int b0 = __float_as_uint(sW[k8 + tig][cbase + nt * 8 + gid]);
                unsigned int b1 = __float_as_uint(sW[k8 + tig + 4][cbase + nt * 8 + gid]);
                mma_tf32(c[0][nt], a[0], b0, b1);
                mma_tf32(c[1][nt], a[1], b0, b1);
            }
        }
    }

    // ---- epilogue: bias + split into Yl/Yr ----
#pragma unroll
    for (int nt = 0; nt < 8; ++nt) {
        int col = cbase + nt * 8 + tig * 2;
        bool isR = col >= 64;
        int lc = isR ? (col - 64) : col;
        float* __restrict__ Y = isR ? g_xr : g_xl;
        const float* __restrict__ Bb = isR ? Br : Bl;
        float bx = __ldg(Bb + lc);
        float by = __ldg(Bb + lc + 1);
#pragma unroll
        for (int t = 0; t < 2; ++t) {
            int r0 = row0 + rbase + t * 16 + gid;
            if (r0 < n) {
                *(float2*)(Y + (size_t)r0 * 64 + lc) =
                    make_float2(c[t][nt][0] + bx, c[t][nt][1] + by);
            }
            int r1 = r0 + 8;
            if (r1 < n) {
                *(float2*)(Y + (size_t)r1 * 64 + lc) =
                    make_float2(c[t][nt][2] + bx, c[t][nt][3] + by);
            }
        }
    }
}

// dual small GEMM: Yl = X@Wl+Bl, Yr = X@Wr+Br, OC=10, K=64. X = g_h2.
__global__ __launch_bounds__(128)
void gemm_small10_dual_kernel(const float* __restrict__ Wl, const float* __restrict__ Bl,
                              const float* __restrict__ Wr, const float* __restrict__ Br,
                              int n)
{
    const float* __restrict__ X = g_h2;
    float* __restrict__ Yl = g_xl;
    float* __restrict__ Yr = g_xr;

    __shared__ float sWl[64][10];
    __shared__ float sWr[64][10];
    __shared__ float sX[128][65];
    int tid = threadIdx.x;
    for (int i = tid; i < 640; i += 128) {
        sWl[i / 10][i % 10] = Wl[i];
        sWr[i / 10][i % 10] = Wr[i];
    }
    int row0 = blockIdx.x * 128;
    for (int i = tid; i < 2048; i += 128) {
        int r = i >> 4, c4 = (i & 15) << 2;
        int gr = row0 + r;
        float4 v = make_float4(0.f, 0.f, 0.f, 0.f);
        if (gr < n) v = *(const float4*)(X + (size_t)gr * 64 + c4);
        sX[r][c4 + 0] = v.x; sX[r][c4 + 1] = v.y;
        sX[r][c4 + 2] = v.z; sX[r][c4 + 3] = v.w;
    }
    __syncthreads();
    int row = row0 + tid;
    float accl[10], accr[10];
#pragma unroll
    for (int c = 0; c < 10; ++c) { accl[c] = 0.f; accr[c] = 0.f; }
#pragma unroll 4
    for (int k = 0; k < 64; ++k) {
        float a = sX[tid][k];
#pragma unroll
        for (int c = 0; c < 10; ++c) {
            accl[c] = fmaf(a, sWl[k][c], accl[c]);
            accr[c] = fmaf(a, sWr[k][c], accr[c]);
        }
    }
    if (row < n) {
#pragma unroll
        for (int c = 0; c < 10; ++c) {
            Yl[(size_t)row * 10 + c] = accl[c] + Bl[c];
            Yr[(size_t)row * 10 + c] = accr[c] + Br[c];
        }
    }
}

// ---------------- GATv2 edge kernel v3, H=2, C=32 ---------------------------
// Warp per node, 4 edges per iteration: slot = lane>>3 (edge), c = lane&7
// (feature chunk: floats [8c, 8c+8) = two float4s). Head 0 = lanes c 0..3,
// head 1 = lanes c 4..7 -> logit reduction is xor 2, xor 1 ONLY (per-head).
// Branchless online softmax per (slot, head); slots merged via xor 8, xor 16
// (flips slot bits only, so merges stay head-consistent).
__global__ __launch_bounds__(256)
void gat_h2c32_kernel(int oid, const float* __restrict__ att,
                      const float* __restrict__ bias, int n)
{
    const float4* __restrict__ xl4 = (const float4*)g_xl;
    float* __restrict__ out = scratch(oid);

    int node = (blockIdx.x * blockDim.x + threadIdx.x) >> 5;
    if (node >= n) return;
    int lane = threadIdx.x & 31;
    int c    = lane & 7;      // chunk pair id (0..7); head = c>>2
    int slot = lane >> 3;     // 0..3

    const float4* xr4 = (const float4*)(g_xr + (size_t)node * 64);
    float4 xrv0 = xr4[2 * c], xrv1 = xr4[2 * c + 1];
    float4 av0 = ((const float4*)att)[2 * c];
    float4 av1 = ((const float4*)att)[2 * c + 1];

    int j  = g_offsets[node];
    const int j1 = g_offsets[node + 1];

    float m = -1e30f, s = 0.f;
    float4 acc0 = make_float4(0.f, 0.f, 0.f, 0.f);
    float4 acc1 = make_float4(0.f, 0.f, 0.f, 0.f);

    int src = g_csr_src[j + slot];
    float4 cur0 = xl4[(size_t)src * 16 + 2 * c];
    float4 cur1 = xl4[(size_t)src * 16 + 2 * c + 1];

    while (j < j1) {
        int jn = j + 4;
        int nsrc = g_csr_src[jn + slot];                   // padded: always safe
        float4 ncur0 = xl4[(size_t)nsrc * 16 + 2 * c];     // prefetch next gather
        float4 ncur1 = xl4[(size_t)nsrc * 16 + 2 * c + 1];

        float v;
        {
            float t;
            t = cur0.x + xrv0.x; v  = lrelu02(t) * av0.x;
            t = cur0.y + xrv0.y; v  = fmaf(lrelu02(t), av0.y, v);
            t = cur0.z + xrv0.z; v  = fmaf(lrelu02(t), av0.z, v);
            t = cur0.w + xrv0.w; v  = fmaf(lrelu02(t), av0.w, v);
            t = cur1.x + xrv1.x; v  = fmaf(lrelu02(t), av1.x, v);
            t = cur1.y + xrv1.y; v  = fmaf(lrelu02(t), av1.y, v);
            t = cur1.z + xrv1.z; v  = fmaf(lrelu02(t), av1.z, v);
            t = cur1.w + xrv1.w; v  = fmaf(lrelu02(t), av1.w, v);
        }
        // per-head reduction: heads occupy 4-lane groups -> xor 2, xor 1 only
        v += __shfl_xor_sync(0xffffffffu, v, 2);
        v += __shfl_xor_sync(0xffffffffu, v, 1);
        if (j + slot >= j1) v = -2e30f;    // ragged-tail sentinel: zero contribution

        float d  = v - m;
        float e  = __expf(-fabsf(d));
        float cf = (d > 0.f) ? e : 1.f;
        float p  = (d > 0.f) ? 1.f : e;
        m = fmaxf(m, v);
        s = fmaf(s, cf, p);
        acc0.x = fmaf(acc0.x, cf, p * cur0.x);
        acc0.y = fmaf(acc0.y, cf, p * cur0.y);
        acc0.z = fmaf(acc0.z, cf, p * cur0.z);
        acc0.w = fmaf(acc0.w, cf, p * cur0.w);
        acc1.x = fmaf(acc1.x, cf, p * cur1.x);
        acc1.y = fmaf(acc1.y, cf, p * cur1.y);
        acc1.z = fmaf(acc1.z, cf, p * cur1.z);
        acc1.w = fmaf(acc1.w, cf, p * cur1.w);

        cur0 = ncur0; cur1 = ncur1;
        j = jn;
    }

    // merge the 4 slot softmax states (stages: xor 8, xor 16; preserves c/head)
#pragma unroll
    for (int off = 8; off <= 16; off <<= 1) {
        float mo = __shfl_xor_sync(0xffffffffu, m, off);
        float nm = fmaxf(m, mo);
        float cf = __expf(m - nm);
        s *= cf;
        acc0.x *= cf; acc0.y *= cf; acc0.z *= cf; acc0.w *= cf;
        acc1.x *= cf; acc1.y *= cf; acc1.z *= cf; acc1.w *= cf;
        s += __shfl_xor_sync(0xffffffffu, s, off);
        acc0.x += __shfl_xor_sync(0xffffffffu, acc0.x, off);
        acc0.y += __shfl_xor_sync(0xffffffffu, acc0.y, off);
        acc0.z += __shfl_xor_sync(0xffffffffu, acc0.z, off);
        acc0.w += __shfl_xor_sync(0xffffffffu, acc0.w, off);
        acc1.x += __shfl_xor_sync(0xffffffffu, acc1.x, off);
        acc1.y += __shfl_xor_sync(0xffffffffu, acc1.y, off);
        acc1.z += __shfl_xor_sync(0xffffffffu, acc1.z, off);
        acc1.w += __shfl_xor_sync(0xffffffffu, acc1.w, off);
        m = nm;
    }

    if (lane < 8) {
        float inv = 1.f / s;
        float4 bv0 = ((const float4*)bias)[2 * c];
        float4 bv1 = ((const float4*)bias)[2 * c + 1];
        float4 o0, o1;
        o0.x = fmaf(acc0.x, inv, bv0.x);
        o0.y = fmaf(acc0.y, inv, bv0.y);
        o0.z = fmaf(acc0.z, inv, bv0.z);
        o0.w = fmaf(acc0.w, inv, bv0.w);
        o1.x = fmaf(acc1.x, inv, bv1.x);
        o1.y = fmaf(acc1.y, inv, bv1.y);
        o1.z = fmaf(acc1.z, inv, bv1.z);
        o1.w = fmaf(acc1.w, inv, bv1.w);
        // epilogue leaky_relu(0.01)
        o0.x = fmaxf(o0.x, 0.f) + 0.01f * fminf(o0.x, 0.f);
        o0.y = fmaxf(o0.y, 0.f) + 0.01f * fminf(o0.y, 0.f);
        o0.z = fmaxf(o0.z, 0.f) + 0.01f * fminf(o0.z, 0.f);
        o0.w = fmaxf(o0.w, 0.f) + 0.01f * fminf(o0.w, 0.f);
        o1.x = fmaxf(o1.x, 0.f) + 0.01f * fminf(o1.x, 0.f);
        o1.y = fmaxf(o1.y, 0.f) + 0.01f * fminf(o1.y, 0.f);
        o1.z = fmaxf(o1.z, 0.f) + 0.01f * fminf(o1.z, 0.f);
        o1.w = fmaxf(o1.w, 0.f) + 0.01f * fminf(o1.w, 0.f);
        float4* o4 = (float4*)(out + (size_t)node * 64);
        o4[2 * c]     = o0;
        o4[2 * c + 1] = o1;
    }
}

// ---------------- GATv2 edge kernel v3, H=1, C=10 (layer 2) -----------------
// 4 edges/iter: slot = lane>>3, c = lane&7; lane owns features {2c, 2c+1},
// active when c < 5. Single head -> full 8-lane reduction (xor 4,2,1) is
// correct (inactive lanes contribute 0 via av=0).
__global__ __launch_bounds__(256)
void gat_h1c10_kernel(const float* __restrict__ att,
                      const float* __restrict__ bias, int n)
{
    const float* __restrict__ xl = g_xl;
    float* __restrict__ out = g_h3;

    int node = (blockIdx.x * blockDim.x + threadIdx.x) >> 5;
    if (node >= n) return;
    int lane = threadIdx.x & 31;
    int c    = lane & 7;
    int slot = lane >> 3;
    bool act = c < 5;

    float2 xrv = make_float2(0.f, 0.f), av = make_float2(0.f, 0.f);
    if (act) {
        xrv = *(const float2*)(g_xr + (size_t)node * 10 + 2 * c);
        av  = *(const float2*)(att + 2 * c);
    }

    int j  = g_offsets[node];
    const int j1 = g_offsets[node + 1];

    float m = -1e30f, s = 0.f;
    float2 acc = make_float2(0.f, 0.f);

    int src = g_csr_src[j + slot];
    float2 cur = act ? *(const float2*)(xl + (size_t)src * 10 + 2 * c)
                     : make_float2(0.f, 0.f);

    while (j < j1) {
        int jn = j + 4;
        int nsrc = g_csr_src[jn + slot];
        float2 ncur = act ? *(const float2*)(xl + (size_t)nsrc * 10 + 2 * c)
                          : make_float2(0.f, 0.f);

        float t0 = cur.x + xrv.x;
        float t1 = cur.y + xrv.y;
        float v = fmaf(lrelu02(t0), av.x, lrelu02(t1) * av.y);
        v += __shfl_xor_sync(0xffffffffu, v, 4);
        v += __shfl_xor_sync(0xffffffffu, v, 2);
        v += __shfl_xor_sync(0xffffffffu, v, 1);
        if (j + slot >= j1) v = -2e30f;

        float d  = v - m;
        float e  = __expf(-fabsf(d));
        float cf = (d > 0.f) ? e : 1.f;
        float p  = (d > 0.f) ? 1.f : e;
        m = fmaxf(m, v);
        s = fmaf(s, cf, p);
        acc.x = fmaf(acc.x, cf, p * cur.x);
        acc.y = fmaf(acc.y, cf, p * cur.y);

        cur = ncur;
        j = jn;
    }

#pragma unroll
    for (int off = 8; off <= 16; off <<= 1) {
        float mo = __shfl_xor_sync(0xffffffffu, m, off);
        float nm = fmaxf(m, mo);
        float cf = __expf(m - nm);
        s *= cf;  acc.x *= cf;  acc.y *= cf;
        s += __shfl_xor_sync(0xffffffffu, s, off);
        acc.x += __shfl_xor_sync(0xffffffffu, acc.x, off);
        acc.y += __shfl_xor_sync(0xffffffffu, acc.y, off);
        m = nm;
    }

    if (lane < 8 && act) {
        float inv = 1.f / s;
        float2 bv = *(const float2*)(bias + 2 * c);
        *(float2*)(out + (size_t)node * 10 + 2 * c) =
            make_float2(fmaf(acc.x, inv, bv.x), fmaf(acc.y, inv, bv.y));
    }
}

// ---------------- pooling: block per graph ----------------------------------
__device__ __forceinline__ int lb_words(const int* a, int n, int key, int is64) {
    int lo = 0, hi = n;
    while (lo < hi) {
        int mid = (lo + hi) >> 1;
        int v = is64 ? a[2 * mid] : a[mid];
        if (v < key) lo = mid + 1; else hi = mid;
    }
    return lo;
}

__global__ __launch_bounds__(256)
void pool_kernel(const int* __restrict__ batch,
                 float* __restrict__ out, int n)
{
    const float* __restrict__ H = g_h3;
    __shared__ int sbeg, send;
    __shared__ float red[8][10];
    int g = blockIdx.x;
    int tid = threadIdx.x;
    int is64 = g_is64;
    if (tid == 0) sbeg = lb_words(batch, n, g, is64);
    if (tid == 1) send = lb_words(batch, n, g + 1, is64);
    __syncthreads();
    int beg = sbeg, end = send;

    float acc[10];
#pragma unroll
    for (int c = 0; c < 10; ++c) acc[c] = 0.f;
    for (int i = beg + tid; i < end; i += 256) {
#pragma unroll
        for (int c = 0; c < 10; ++c) acc[c] += H[(size_t)i * 10 + c];
    }
#pragma unroll
    for (int c = 0; c < 10; ++c) {
        acc[c] += __shfl_xor_sync(0xffffffffu, acc[c], 16);
        acc[c] += __shfl_xor_sync(0xffffffffu, acc[c], 8);
        acc[c] += __shfl_xor_sync(0xffffffffu, acc[c], 4);
        acc[c] += __shfl_xor_sync(0xffffffffu, acc[c], 2);
        acc[c] += __shfl_xor_sync(0xffffffffu, acc[c], 1);
    }
    int wid = tid >> 5, lane = tid & 31;
    if (lane == 0) {
#pragma unroll
        for (int c = 0; c < 10; ++c) red[wid][c] = acc[c];
    }
    __syncthreads();
    if (tid < 10) {
        float s = 0.f;
#pragma unroll
        for (int w = 0; w < 8; ++w) s += red[w][tid];
        float cnt = (float)(end - beg);
        if (cnt < 1.f) cnt = 1.f;
        out[g * 10 + tid] = s / cnt;
    }
}

// ---------------- launch -----------------------------------------------------
extern "C" void kernel_launch(void* const* d_in, const int* in_sizes, int n_in,
                              void* d_out, int out_size)
{
    const float* x     = (const float*)d_in[0];
    const int*   ei    = (const int*)d_in[1];    // int32 words (int64 handled via sniff)
    const int*   batch = (const int*)d_in[2];
    const float* Wl0 = (const float*)d_in[3];
    const float* bl0 = (const float*)d_in[4];
    const float* Wr0 = (const float*)d_in[5];
    const float* br0 = (const float*)d_in[6];
    const float* att0= (const float*)d_in[7];
    const float* b0  = (const float*)d_in[8];
    const float* Wl1 = (const float*)d_in[9];
    const float* bl1 = (const float*)d_in[10];
    const float* Wr1 = (const float*)d_in[11];
    const float* br1 = (const float*)d_in[12];
    const float* att1= (const float*)d_in[13];
    const float* b1  = (const float*)d_in[14];
    const float* Wl2 = (const float*)d_in[15];
    const float* bl2 = (const float*)d_in[16];
    const float* Wr2 = (const float*)d_in[17];
    const float* br2 = (const float*)d_in[18];
    const float* att2= (const float*)d_in[19];
    const float* b2  = (const float*)d_in[20];
    float* out = (float*)d_out;

    const int n = NN;

    // ---- CSR build: init+sniff, hist(2x), 2-kernel scan, scatter(2x) ----
    init_kernel<<<(n + 255) / 256, 256>>>(ei, n);
    hist_kernel<<<(NE / 2 + 255) / 256, 256>>>(ei);
    scan_reduce_kernel<<<SBLOCKS, SCHUNK>>>(n);
    scan_apply_kernel<<<SBLOCKS, SCHUNK>>>(n);
    scatter_kernel<<<(NE / 2 + 255) / 256, 256>>>(ei);

    const int gemm_grid = (n + 127) / 128;
    const int gat_grid  = (n + 7) / 8;        // 8 warps/block

    // ---- layer 0 ----  (x -> xl, xr; gat -> h1(2))
    gemm_dual_tf32_kernel<128><<<gemm_grid, 256>>>(x, -1, Wl0, bl0, Wr0, br0, n);
    gat_h2c32_kernel<<<gat_grid, 256>>>(2, att0, b0, n);

    // ---- layer 1 ----  (h1(2) -> xl, xr; gat -> h2(3))
    gemm_dual_tf32_kernel<64><<<gemm_grid, 256>>>(nullptr, 2, Wl1, bl1, Wr1, br1, n);
    gat_h2c32_kernel<<<gat_grid, 256>>>(3, att1, b1, n);

    // ---- layer 2 ----  (h2(3) -> xl, xr; gat -> h3)
    gemm_small10_dual_kernel<<<gemm_grid, 128>>>(Wl2, bl2, Wr2, br2, n);
    gat_h1c10_kernel<<<gat_grid, 256>>>(att2, b2, n);

    // ---- pooling ----
    pool_kernel<<<NGRAPHS, 256>>>(batch, out, n);
}